// round 14
// baseline (speedup 1.0000x reference)
#include <cuda_runtime.h>
#include <cuda_fp16.h>
#include <cstdint>
#include <math.h>

#define SEQ  2048
#define DM   1024
#define NH   16
#define HD   64
#define DFF  4096

// ---------------- scratch (no allocation allowed) ----------------
__device__ __half g_normed [SEQ * DM];
__device__ __half g_q      [NH * SEQ * HD];
__device__ __half g_k      [NH * SEQ * HD];
__device__ __half g_v      [NH * SEQ * HD];
__device__ __half g_attn   [SEQ * DM];
__device__ float  g_x2     [SEQ * DM];
__device__ __half g_normed2[SEQ * DM];
__device__ __half g_ffh    [SEQ * DFF];
// fp16 weight copies
__device__ __half g_wqkv_h [DM * 3 * DM];
__device__ __half g_wout_h [DM * DM];
__device__ __half g_wff1_h [DM * DFF];
__device__ __half g_wff2_h [DFF * DM];

// ---------------- helpers ----------------
__device__ __forceinline__ unsigned h2u(__half2 h) { return *reinterpret_cast<unsigned*>(&h); }

__device__ __forceinline__ void mma16(float* d, const unsigned* a, const unsigned* b) {
    asm volatile(
        "mma.sync.aligned.m16n8k16.row.col.f32.f16.f16.f32 "
        "{%0,%1,%2,%3}, {%4,%5,%6,%7}, {%8,%9}, {%0,%1,%2,%3};\n"
        : "+f"(d[0]), "+f"(d[1]), "+f"(d[2]), "+f"(d[3])
        : "r"(a[0]), "r"(a[1]), "r"(a[2]), "r"(a[3]), "r"(b[0]), "r"(b[1]));
}
__device__ __forceinline__ void cp16(void* sdst, const void* gsrc) {
    unsigned int d = (unsigned int)__cvta_generic_to_shared(sdst);
    asm volatile("cp.async.cg.shared.global [%0], [%1], 16;\n" :: "r"(d), "l"(gsrc));
}
__device__ __forceinline__ void ldsm4(unsigned* r, const void* saddr) {
    unsigned int ad = (unsigned int)__cvta_generic_to_shared(saddr);
    asm volatile("ldmatrix.sync.aligned.m8n8.x4.shared.b16 {%0,%1,%2,%3}, [%4];\n"
        : "=r"(r[0]), "=r"(r[1]), "=r"(r[2]), "=r"(r[3]) : "r"(ad));
}
__device__ __forceinline__ void ldsm4t(unsigned* r, const void* saddr) {
    unsigned int ad = (unsigned int)__cvta_generic_to_shared(saddr);
    asm volatile("ldmatrix.sync.aligned.m8n8.x4.trans.shared.b16 {%0,%1,%2,%3}, [%4];\n"
        : "=r"(r[0]), "=r"(r[1]), "=r"(r[2]), "=r"(r[3]) : "r"(ad));
}

// ---------------- fused weight fp32 -> fp16 convert ----------------
__global__ __launch_bounds__(256) void cvt_all_kernel(
    const float* __restrict__ s0, __half* __restrict__ d0, int n0,
    const float* __restrict__ s1, __half* __restrict__ d1, int n1,
    const float* __restrict__ s2, __half* __restrict__ d2, int n2,
    const float* __restrict__ s3, __half* __restrict__ d3, int n3)
{
    int i = blockIdx.x * blockDim.x + threadIdx.x;
    int stride = gridDim.x * blockDim.x;
    #define CVT_LOOP(S, D, N) \
    for (int j = i; j < N; j += stride) { \
        float4 v = reinterpret_cast<const float4*>(S)[j]; \
        __half2 lo = __floats2half2_rn(v.x, v.y); \
        __half2 hi = __floats2half2_rn(v.z, v.w); \
        reinterpret_cast<uint2*>(D)[j] = make_uint2(h2u(lo), h2u(hi)); \
    }
    CVT_LOOP(s0, d0, n0) CVT_LOOP(s1, d1, n1) CVT_LOOP(s2, d2, n2) CVT_LOOP(s3, d3, n3)
    #undef CVT_LOOP
}

// ---------------- LayerNorm (fp16 output: feeds GEMM A) ----------------
__global__ __launch_bounds__(256) void ln_kernel(
    const float* __restrict__ x, const float* __restrict__ g,
    const float* __restrict__ b, __half* __restrict__ out)
{
    int row = blockIdx.x;
    int tid = threadIdx.x;
    const float* xr = x + (size_t)row * DM;
    float4 xv = reinterpret_cast<const float4*>(xr)[tid];
    float s  = xv.x + xv.y + xv.z + xv.w;
    float sq = xv.x*xv.x + xv.y*xv.y + xv.z*xv.z + xv.w*xv.w;

    __shared__ float sh1[256], sh2[256];
    sh1[tid] = s; sh2[tid] = sq;
    __syncthreads();
    #pragma unroll
    for (int o = 128; o > 0; o >>= 1) {
        if (tid < o) { sh1[tid] += sh1[tid + o]; sh2[tid] += sh2[tid + o]; }
        __syncthreads();
    }
    float mu   = sh1[0] * (1.0f / DM);
    float var  = sh2[0] * (1.0f / DM) - mu * mu;
    float rstd = rsqrtf(var + 1e-5f);

    float4 gv = reinterpret_cast<const float4*>(g)[tid];
    float4 bv = reinterpret_cast<const float4*>(b)[tid];
    __half2 lo = __floats2half2_rn((xv.x - mu) * rstd * gv.x + bv.x,
                                   (xv.y - mu) * rstd * gv.y + bv.y);
    __half2 hi = __floats2half2_rn((xv.z - mu) * rstd * gv.z + bv.z,
                                   (xv.w - mu) * rstd * gv.w + bv.w);
    reinterpret_cast<uint2*>(out + (size_t)row * DM)[tid] = make_uint2(h2u(lo), h2u(hi));
}

// ---------------- fp16 MMA GEMM: TM x 128 block, 8 warps, BK=32 --------------
// OP = 1: float C = A*B + bias + res; OP = 2: half C = gelu(A*B + bias)
// OP = 3: QKV epilogue — L2-normalize q,k; write [H,L,64] layout
#define ASTR 40
#define BSTR 136
#define HBK  32
#define GNST 3

template<int TM, int OP>
__global__ __launch_bounds__(256) void hgemm(
    const __half* __restrict__ A, const __half* __restrict__ B,
    const float* __restrict__ bias, const float* __restrict__ res,
    void* __restrict__ Cv, __half* __restrict__ Qo, __half* __restrict__ Ko,
    __half* __restrict__ Vo, int M, int N, int K)
{
    constexpr int NWN   = (TM == 128) ? 2 : 4;
    constexpr int NT    = 16 / NWN;
    constexpr int STAGE = TM * ASTR + HBK * BSTR;

    extern __shared__ __half sh[];

    const int tid  = threadIdx.x;
    const int lane = tid & 31;
    const int warp = tid >> 5;
    const int g    = lane >> 2;
    const int tig  = lane & 3;
    const int wm   = warp / NWN;
    const int wn   = warp % NWN;
    const int m0   = blockIdx.x * TM;
    const int n0   = blockIdx.y * 128;

    const int lt = lane >> 3;
    const int li = lane & 7;
    const int arow_l = wm * 32 + (lt & 1) * 8 + li;
    const int acol_l = (lt >> 1) * 8;
    const int brow_l = (lt & 1) * 8 + li;
    const int bcol_l = wn * (NT * 8) + (lt >> 1) * 8;

    float acc[2][NT][4];
    #pragma unroll
    for (int mt = 0; mt < 2; mt++)
        #pragma unroll
        for (int nt = 0; nt < NT; nt++)
            #pragma unroll
            for (int i = 0; i < 4; i++) acc[mt][nt][i] = 0.0f;

    const int nsteps = K >> 5;

    #define LOAD_STAGE(sp, kt) do { \
        __half* As = sh + (sp) * STAGE; \
        __half* Bs = As + TM * ASTR; \
        _Pragma("unroll") \
        for (int t = 0; t < TM / 64; t++) { \
            int idx = t * 256 + tid; \
            int arw = idx >> 2, aof = (idx & 3) * 8; \
            cp16(&As[arw * ASTR + aof], A + (size_t)(m0 + arw) * K + (kt) + aof); \
        } \
        _Pragma("unroll") \
        for (int t = 0; t < 2; t++) { \
            int idx = t * 256 + tid; \
            int brw = idx >> 4, bof = (idx & 15) * 8; \
            cp16(&Bs[brw * BSTR + bof], B + (size_t)((kt) + brw) * N + n0 + bof); \
        } \
        asm volatile("cp.async.commit_group;\n"); \
    } while (0)

    #pragma unroll
    for (int s = 0; s < GNST - 1; s++) LOAD_STAGE(s, s * HBK);

    for (int it = 0; it < nsteps; it++) {
        asm volatile("cp.async.wait_group %0;\n" :: "n"(GNST - 2));
        __syncthreads();

        if (it + GNST - 1 < nsteps)
            LOAD_STAGE((it + GNST - 1) % GNST, (it + GNST - 1) * HBK);
        else
            asm volatile("cp.async.commit_group;\n");

        const __half* As = sh + (it % GNST) * STAGE;
        const __half* Bs = As + TM * ASTR;

        #pragma unroll
        for (int kb = 0; kb < HBK; kb += 16) {
            unsigned a[2][4], b[NT][2];
            ldsm4(a[0], &As[arow_l * ASTR + kb + acol_l]);
            ldsm4(a[1], &As[(arow_l + 16) * ASTR + kb + acol_l]);
            #pragma unroll
            for (int ntp = 0; ntp < NT / 2; ntp++) {
                unsigned t4[4];
                ldsm4t(t4, &Bs[(kb + brow_l) * BSTR + bcol_l + ntp * 16]);
                b[2 * ntp][0]     = t4[0]; b[2 * ntp][1]     = t4[1];
                b[2 * ntp + 1][0] = t4[2]; b[2 * ntp + 1][1] = t4[3];
            }
            #pragma unroll
            for (int mt = 0; mt < 2; mt++)
                #pragma unroll
                for (int nt = 0; nt < NT; nt++)
                    mma16(acc[mt][nt], a[mt], b[nt]);
        }
    }
    #undef LOAD_STAGE

    // ---------------- epilogue ----------------
    if (OP == 3) {
        const int grp = (n0 >> 6) + wn;
        const int cls = grp >> 4;
        const int hh  = grp & 15;
        __half* Dst = (cls == 0) ? Qo : (cls == 1) ? Ko : Vo;

        #pragma unroll
        for (int mt = 0; mt < 2; mt++) {
            const int r0 = m0 + wm * 32 + mt * 16 + g;
            const int r1 = r0 + 8;
            float v[NT][4];
            float ss0 = 0.0f, ss1 = 0.0f;
            #pragma unroll
            for (int nt = 0; nt < NT; nt++) {
                const int c = n0 + wn * (NT * 8) + nt * 8 + tig * 2;
                const float b0 = bias[c], b1 = bias[c + 1];
                v[nt][0] = acc[mt][nt][0] + b0;
                v[nt][1] = acc[mt][nt][1] + b1;
                v[nt][2] = acc[mt][nt][2] + b0;
                v[nt][3] = acc[mt][nt][3] + b1;
                ss0 += v[nt][0] * v[nt][0] + v[nt][1] * v[nt][1];
                ss1 += v[nt][2] * v[nt][2] + v[nt][3] * v[nt][3];
            }
            ss0 += __shfl_xor_sync(0xffffffffu, ss0, 1);
            ss0 += __shfl_xor_sync(0xffffffffu, ss0, 2);
            ss1 += __shfl_xor_sync(0xffffffffu, ss1, 1);
            ss1 += __shfl_xor_sync(0xffffffffu, ss1, 2);
            float sc0 = 1.0f, sc1 = 1.0f;
            if (cls == 0) {
                sc0 = 0.125f / fmaxf(sqrtf(ss0), 1e-12f);
                sc1 = 0.125f / fmaxf(sqrtf(ss1), 1e-12f);
            } else if (cls == 1) {
                sc0 = 1.0f / fmaxf(sqrtf(ss0), 1e-12f);
                sc1 = 1.0f / fmaxf(sqrtf(ss1), 1e-12f);
            }
            __half* d0p = Dst + ((size_t)hh * SEQ + r0) * HD + tig * 2;
            __half* d1p = Dst + ((size_t)hh * SEQ + r1) * HD + tig * 2;
            #pragma unroll
            for (int nt = 0; nt < NT; nt++) {
                *reinterpret_cast<unsigned*>(d0p + nt * 8) =
                    h2u(__floats2half2_rn(v[nt][0] * sc0, v[nt][1] * sc0));
                *reinterpret_cast<unsigned*>(d1p + nt * 8) =
                    h2u(__floats2half2_rn(v[nt][2] * sc1, v[nt][3] * sc1));
            }
        }
        return;
    }

    #pragma unroll
    for (int mt = 0; mt < 2; mt++) {
        const int r0 = m0 + wm * 32 + mt * 16 + g;
        const int r1 = r0 + 8;
        #pragma unroll
        for (int nt = 0; nt < NT; nt++) {
            const int c = n0 + wn * (NT * 8) + nt * 8 + tig * 2;
            const float b0 = bias[c], b1 = bias[c + 1];
            float v0 = acc[mt][nt][0] + b0;
            float v1 = acc[mt][nt][1] + b1;
            float v2 = acc[mt][nt][2] + b0;
            float v3 = acc[mt][nt][3] + b1;
            if (OP == 1) {
                float* Cf = (float*)Cv;
                const float2 ra = *reinterpret_cast<const float2*>(res + (size_t)r0 * N + c);
                const float2 rb = *reinterpret_cast<const float2*>(res + (size_t)r1 * N + c);
                *reinterpret_cast<float2*>(Cf + (size_t)r0 * N + c) = make_float2(v0 + ra.x, v1 + ra.y);
                *reinterpret_cast<float2*>(Cf + (size_t)r1 * N + c) = make_float2(v2 + rb.x, v3 + rb.y);
            } else {
                if (OP == 2) {
                    v0 = 0.5f * v0 * (1.0f + erff(v0 * 0.70710678118654752f));
                    v1 = 0.5f * v1 * (1.0f + erff(v1 * 0.70710678118654752f));
                    v2 = 0.5f * v2 * (1.0f + erff(v2 * 0.70710678118654752f));
                    v3 = 0.5f * v3 * (1.0f + erff(v3 * 0.70710678118654752f));
                }
                __half* Ch = (__half*)Cv;
                *reinterpret_cast<unsigned*>(Ch + (size_t)r0 * N + c) = h2u(__floats2half2_rn(v0, v1));
                *reinterpret_cast<unsigned*>(Ch + (size_t)r1 * N + c) = h2u(__floats2half2_rn(v2, v3));
            }
        }
    }
}

// ---------------- fp16 MMA attention: 64-query blocks, 4 warps ---------------
// half2 softmax + denominator via ones-column MMA; double-buffered cp.async K/V.
// 512 CTAs, ~45KB smem, 4 CTAs/SM -> 2x occupancy vs 128-row version.
#define QSTR 72
#define KVSTAGE (64 * QSTR)
__global__ __launch_bounds__(128) void attn_h_kernel(
    const __half* __restrict__ Q, const __half* __restrict__ Km,
    const __half* __restrict__ V, const float* __restrict__ lcc,
    __half* __restrict__ out)
{
    extern __shared__ __half apool[];
    __half* Qs = apool;                   // [64][QSTR]
    __half* Kb = apool + 64 * QSTR;       // [2][64][QSTR]
    __half* Vb = Kb + 2 * KVSTAGE;        // [2][64][QSTR]
    __shared__ __half2 lccs[2][32];

    const int h    = blockIdx.y;
    const int m0   = blockIdx.x * 64;
    const int tid  = threadIdx.x;
    const int lane = tid & 31;
    const int warp = tid >> 5;            // 0..3, 16 q-rows each
    const int g    = lane >> 2;
    const int tig  = lane & 3;
    const int lt   = lane >> 3;
    const int li   = lane & 7;

    const int kb_n = ((lane >> 4) << 3) + li;
    const int kb_k = ((lane >> 3) & 1) * 8;

    const __half* Kg = Km + (size_t)h * SEQ * HD;
    const __half* Vg = V  + (size_t)h * SEQ * HD;

    #define LOAD_KV(sb, kt) do { \
        __half* Kd = Kb + (sb) * KVSTAGE; \
        __half* Vd = Vb + (sb) * KVSTAGE; \
        _Pragma("unroll") \
        for (int t = 0; t < 4; t++) { \
            int idx = t * 128 + tid; \
            int row = idx >> 3; \
            int off = (idx & 7) * 8; \
            cp16(&Kd[row * QSTR + off], Kg + (size_t)((kt) + row) * HD + off); \
            cp16(&Vd[row * QSTR + off], Vg + (size_t)((kt) + row) * HD + off); \
        } \
        asm volatile("cp.async.commit_group;\n"); \
        if (tid < 32) { \
            float e0 = __expf(lcc[(kt) + 2 * tid]     * 0.05f); \
            float e1 = __expf(lcc[(kt) + 2 * tid + 1] * 0.05f); \
            lccs[sb][tid] = __floats2half2_rn(e0, e1); \
        } \
    } while (0)

    LOAD_KV(0, 0);

    {
        const __half* Qg = Q + ((size_t)h * SEQ + m0) * HD;
        #pragma unroll
        for (int t = 0; t < 4; t++) {
            int idx = t * 128 + tid;      // 512 chunks of 16B
            int row = idx >> 3;
            int off = (idx & 7) * 8;
            *reinterpret_cast<uint4*>(&Qs[row * QSTR + off]) =
                *reinterpret_cast<const uint4*>(Qg + (size_t)row * HD + off);
        }
    }
    __syncthreads();

    unsigned qa[4][4];
    {
        const int qrow = warp * 16 + (lt & 1) * 8 + li;
        const int qcol = (lt >> 1) * 8;
        #pragma unroll
        for (int kc = 0; kc < 4; kc++)
            ldsm4(qa[kc], &Qs[qrow * QSTR + kc * 16 + qcol]);
    }

    float o[8][4];
    #pragma unroll
    for (int nt = 0; nt < 8; nt++)
        #pragma unroll
        for (int i = 0; i < 4; i++) o[nt][i] = 0.0f;
    float dacc[4] = {0.0f, 0.0f, 0.0f, 0.0f};
    const unsigned ones2 = h2u(__floats2half2_rn(1.0f, 1.0f));
    const unsigned b_ones[2] = {ones2, ones2};

    for (int ti = 0; ti < SEQ / 64; ti++) {
        const int buf = ti & 1;
        __syncthreads();
        if (ti + 1 < SEQ / 64) {
            LOAD_KV(buf ^ 1, (ti + 1) * 64);
        } else {
            asm volatile("cp.async.commit_group;\n");
        }
        asm volatile("cp.async.wait_group 1;\n");
        __syncthreads();

        const __half* Ks = Kb + buf * KVSTAGE;
        const __half* Vs = Vb + buf * KVSTAGE;

        float s[8][4];
        #pragma unroll
        for (int nt = 0; nt < 8; nt++)
            #pragma unroll
            for (int i = 0; i < 4; i++) s[nt][i] = 0.0f;

        #pragma unroll
        for (int kc = 0; kc < 4; kc++) {
            #pragma unroll
            for (int ng = 0; ng < 4; ng++) {
                unsigned t4[4];
                ldsm4(t4, &Ks[(ng * 16 + kb_n) * QSTR + kc * 16 + kb_k]);
                mma16(s[2 * ng],     qa[kc], t4);
                mma16(s[2 * ng + 1], qa[kc], t4 + 2);
            }
        }

        unsigned pa[8][2];
        #pragma unroll
        for (int nt = 0; nt < 8; nt++) {
            __half2 ec = lccs[buf][nt * 4 + tig];
            __half2 p01 = __hmul2(h2exp(__floats2half2_rn(s[nt][0], s[nt][1])), ec);
            __half2 p23 = __hmul2(h2exp(__floats2half2_rn(s[nt][2], s[nt][3])), ec);
            pa[nt][0] = h2u(p01);
            pa[nt][1] = h2u(p23);
        }

        #pragma unroll
        for (int kc = 0; kc < 4; kc++) {
            unsigned a[4];
            a[0] = pa[2 * kc][0];
            a[1] = pa[2 * kc][1];
            a[2] = pa[2 * kc + 1][0];
            a[3] = pa[2 * kc + 1][1];
            mma16(dacc, a, b_ones);
            unsigned vb[8][2];
            #pragma unroll
            for (int ntp = 0; ntp < 4; ntp++) {
                unsigned t4[4];
                ldsm4t(t4, &Vs[(kc * 16 + (lt & 1) * 8 + li) * QSTR + (ntp * 2 + (lt >> 1)) * 8]);
                vb[2 * ntp][0]     = t4[0]; vb[2 * ntp][1]     = t4[1];
                vb[2 * ntp + 1][0] = t4[2]; vb[2 * ntp + 1][1] = t4[3];
            }
            #pragma unroll
            for (int nt = 0; nt < 8; nt++)
                mma16(o[nt], a, vb[nt]);
        }
    }
    #undef LOAD_KV

    const float inv0 = 1.0f / dacc[0];
    const float inv1 = 1.0f / dacc[2];

    const int r0 = m0 + warp * 16 + g;
    const int r1 = r0 + 8;
    #pragma unroll
    for (int nt = 0; nt < 8; nt++) {
        const int c = h * HD + nt * 8 + tig * 2;
        *reinterpret_cast<unsigned*>(out + (size_t)r0 * DM + c) =
            h2u(__floats2half2_rn(o[nt][0] * inv0, o[nt][1] * inv0));
        *reinterpret_cast<unsigned*>(out + (size_t)r1 * DM + c) =
            h2u(__floats2half2_rn(o[nt][2] * inv1, o[nt][3] * inv1));
    }
}

// ---------------- launch --------------------------------------------------------
extern "C" void kernel_launch(void* const* d_in, const int* in_sizes, int n_in,
                              void* d_out, int out_size)
{
    const float* x     = (const float*)d_in[0];
    const float* lcc   = (const float*)d_in[1];
    const float* w_qkv = (const float*)d_in[2];
    const float* b_qkv = (const float*)d_in[3];
    const float* w_out = (const float*)d_in[4];
    const float* b_out = (const float*)d_in[5];
    const float* ln1_g = (const float*)d_in[6];
    const float* ln1_b = (const float*)d_in[7];
    const float* ln2_g = (const float*)d_in[8];
    const float* ln2_b = (const float*)d_in[9];
    const float* w_ff1 = (const float*)d_in[10];
    const float* b_ff1 = (const float*)d_in[11];
    const float* w_ff2 = (const float*)d_in[12];
    const float* b_ff2 = (const float*)d_in[13];
    float* out = (float*)d_out;

    __half *normed, *q, *k, *v, *attn, *normed2, *ffh;
    __half *wqkv_h, *wout_h, *wff1_h, *wff2_h;
    float *x2;
    cudaGetSymbolAddress((void**)&normed,  g_normed);
    cudaGetSymbolAddress((void**)&q,       g_q);
    cudaGetSymbolAddress((void**)&k,       g_k);
    cudaGetSymbolAddress((void**)&v,       g_v);
    cudaGetSymbolAddress((void**)&attn,    g_attn);
    cudaGetSymbolAddress((void**)&x2,      g_x2);
    cudaGetSymbolAddress((void**)&normed2, g_normed2);
    cudaGetSymbolAddress((void**)&ffh,     g_ffh);
    cudaGetSymbolAddress((void**)&wqkv_h,  g_wqkv_h);
    cudaGetSymbolAddress((void**)&wout_h,  g_wout_h);
    cudaGetSymbolAddress((void**)&wff1_h,  g_wff1_h);
    cudaGetSymbolAddress((void**)&wff2_h,  g_wff2_h);

    const int smem128 = GNST * (128 * ASTR + HBK * BSTR) * 2;
    const int smem64  = GNST * (64 * ASTR + HBK * BSTR) * 2;
    cudaFuncSetAttribute((const void*)hgemm<128,3>, cudaFuncAttributeMaxDynamicSharedMemorySize, smem128);
    cudaFuncSetAttribute((const void*)hgemm<128,2>, cudaFuncAttributeMaxDynamicSharedMemorySize, smem128);
    cudaFuncSetAttribute((const void*)hgemm<64,1>,  cudaFuncAttributeMaxDynamicSharedMemorySize, smem64);

    const int asmem = (64 * QSTR + 4 * KVSTAGE) * 2;
    cudaFuncSetAttribute(attn_h_kernel, cudaFuncAttributeMaxDynamicSharedMemorySize, asmem);

    // 0. convert all weights to fp16
    cvt_all_kernel<<<1184, 256>>>(
        w_qkv, wqkv_h, DM * 3 * DM / 4,
        w_out, wout_h, DM * DM / 4,
        w_ff1, wff1_h, DM * DFF / 4,
        w_ff2, wff2_h, DFF * DM / 4);

    // 1. LN1 (fp16 output)
    ln_kernel<<<SEQ, 256>>>(x, ln1_g, ln1_b, normed);
    // 2. QKV projection + fused split/cosine-normalize/relayout
    hgemm<128,3><<<dim3(SEQ / 128, 3 * DM / 128), 256, smem128>>>(
        normed, wqkv_h, b_qkv, nullptr, nullptr, q, k, v, SEQ, 3 * DM, DM);
    // 3. attention (fp16 MMA, 64-row blocks, 4 CTAs/SM)
    attn_h_kernel<<<dim3(SEQ / 64, NH), 128, asmem>>>(q, k, v, lcc, attn);
    // 4. out projection + residual (fp32 out) — 64-row tiles
    hgemm<64,1><<<dim3(SEQ / 64, DM / 128), 256, smem64>>>(
        attn, wout_h, b_out, x, x2, nullptr, nullptr, nullptr, SEQ, DM, DM);
    // 5. LN2 (fp16 output)
    ln_kernel<<<SEQ, 256>>>(x2, ln2_g, ln2_b, normed2);
    // 6. FF1 + exact GELU (fp16 output)
    hgemm<128,2><<<dim3(SEQ / 128, DFF / 128), 256, smem128>>>(
        normed2, wff1_h, b_ff1, nullptr, ffh, nullptr, nullptr, nullptr, SEQ, DFF, DM);
    // 7. FF2 + residual -> out (fp32) — 64-row tiles
    hgemm<64,1><<<dim3(SEQ / 64, DM / 128), 256, smem64>>>(
        ffh, wff2_h, b_ff2, x2, out, nullptr, nullptr, nullptr, SEQ, DM, DFF);
}

// round 15
// speedup vs baseline: 1.0066x; 1.0066x over previous
#include <cuda_runtime.h>
#include <cuda_fp16.h>
#include <cstdint>
#include <math.h>

#define SEQ  2048
#define DM   1024
#define NH   16
#define HD   64
#define DFF  4096

// ---------------- scratch (no allocation allowed) ----------------
__device__ __half g_normed [SEQ * DM];
__device__ __half g_q      [NH * SEQ * HD];
__device__ __half g_k      [NH * SEQ * HD];
__device__ __half g_v      [NH * SEQ * HD];
__device__ __half g_attn   [SEQ * DM];
__device__ float  g_x2     [SEQ * DM];
__device__ __half g_normed2[SEQ * DM];
__device__ __half g_ffh    [SEQ * DFF];
// fp16 weight copies
__device__ __half g_wqkv_h [DM * 3 * DM];
__device__ __half g_wout_h [DM * DM];
__device__ __half g_wff1_h [DM * DFF];
__device__ __half g_wff2_h [DFF * DM];

// ---------------- helpers ----------------
__device__ __forceinline__ unsigned h2u(__half2 h) { return *reinterpret_cast<unsigned*>(&h); }
__device__ __forceinline__ __half2 u2h(unsigned u) { return *reinterpret_cast<__half2*>(&u); }

__device__ __forceinline__ void mma16(float* d, const unsigned* a, const unsigned* b) {
    asm volatile(
        "mma.sync.aligned.m16n8k16.row.col.f32.f16.f16.f32 "
        "{%0,%1,%2,%3}, {%4,%5,%6,%7}, {%8,%9}, {%0,%1,%2,%3};\n"
        : "+f"(d[0]), "+f"(d[1]), "+f"(d[2]), "+f"(d[3])
        : "r"(a[0]), "r"(a[1]), "r"(a[2]), "r"(a[3]), "r"(b[0]), "r"(b[1]));
}
// fp16-accumulator variant: D,C are 2 packed b32 regs
__device__ __forceinline__ void mma16h(unsigned* d, const unsigned* a, const unsigned* b) {
    asm volatile(
        "mma.sync.aligned.m16n8k16.row.col.f16.f16.f16.f16 "
        "{%0,%1}, {%2,%3,%4,%5}, {%6,%7}, {%0,%1};\n"
        : "+r"(d[0]), "+r"(d[1])
        : "r"(a[0]), "r"(a[1]), "r"(a[2]), "r"(a[3]), "r"(b[0]), "r"(b[1]));
}
__device__ __forceinline__ void cp16(void* sdst, const void* gsrc) {
    unsigned int d = (unsigned int)__cvta_generic_to_shared(sdst);
    asm volatile("cp.async.cg.shared.global [%0], [%1], 16;\n" :: "r"(d), "l"(gsrc));
}
__device__ __forceinline__ void ldsm4(unsigned* r, const void* saddr) {
    unsigned int ad = (unsigned int)__cvta_generic_to_shared(saddr);
    asm volatile("ldmatrix.sync.aligned.m8n8.x4.shared.b16 {%0,%1,%2,%3}, [%4];\n"
        : "=r"(r[0]), "=r"(r[1]), "=r"(r[2]), "=r"(r[3]) : "r"(ad));
}
__device__ __forceinline__ void ldsm4t(unsigned* r, const void* saddr) {
    unsigned int ad = (unsigned int)__cvta_generic_to_shared(saddr);
    asm volatile("ldmatrix.sync.aligned.m8n8.x4.trans.shared.b16 {%0,%1,%2,%3}, [%4];\n"
        : "=r"(r[0]), "=r"(r[1]), "=r"(r[2]), "=r"(r[3]) : "r"(ad));
}

// ---------------- fused LN1 + weight convert (one launch, concurrent) ----------
__global__ __launch_bounds__(256) void ln_cvt_kernel(
    const float* __restrict__ x, const float* __restrict__ g,
    const float* __restrict__ b, __half* __restrict__ out,
    const float* __restrict__ s0, __half* __restrict__ d0, int n0,
    const float* __restrict__ s1, __half* __restrict__ d1, int n1,
    const float* __restrict__ s2, __half* __restrict__ d2, int n2,
    const float* __restrict__ s3, __half* __restrict__ d3, int n3)
{
    int tid = threadIdx.x;
    if (blockIdx.x < SEQ) {
        int row = blockIdx.x;
        const float* xr = x + (size_t)row * DM;
        float4 xv = reinterpret_cast<const float4*>(xr)[tid];
        float s  = xv.x + xv.y + xv.z + xv.w;
        float sq = xv.x*xv.x + xv.y*xv.y + xv.z*xv.z + xv.w*xv.w;

        __shared__ float sh1[256], sh2[256];
        sh1[tid] = s; sh2[tid] = sq;
        __syncthreads();
        #pragma unroll
        for (int o = 128; o > 0; o >>= 1) {
            if (tid < o) { sh1[tid] += sh1[tid + o]; sh2[tid] += sh2[tid + o]; }
            __syncthreads();
        }
        float mu   = sh1[0] * (1.0f / DM);
        float var  = sh2[0] * (1.0f / DM) - mu * mu;
        float rstd = rsqrtf(var + 1e-5f);

        float4 gv = reinterpret_cast<const float4*>(g)[tid];
        float4 bv = reinterpret_cast<const float4*>(b)[tid];
        __half2 lo = __floats2half2_rn((xv.x - mu) * rstd * gv.x + bv.x,
                                       (xv.y - mu) * rstd * gv.y + bv.y);
        __half2 hi = __floats2half2_rn((xv.z - mu) * rstd * gv.z + bv.z,
                                       (xv.w - mu) * rstd * gv.w + bv.w);
        reinterpret_cast<uint2*>(out + (size_t)row * DM)[tid] = make_uint2(h2u(lo), h2u(hi));
        return;
    }
    int i = (blockIdx.x - SEQ) * blockDim.x + tid;
    int stride = (gridDim.x - SEQ) * blockDim.x;
    #define CVT_LOOP(S, D, N) \
    for (int j = i; j < N; j += stride) { \
        float4 v = reinterpret_cast<const float4*>(S)[j]; \
        __half2 lo = __floats2half2_rn(v.x, v.y); \
        __half2 hi = __floats2half2_rn(v.z, v.w); \
        reinterpret_cast<uint2*>(D)[j] = make_uint2(h2u(lo), h2u(hi)); \
    }
    CVT_LOOP(s0, d0, n0) CVT_LOOP(s1, d1, n1) CVT_LOOP(s2, d2, n2) CVT_LOOP(s3, d3, n3)
    #undef CVT_LOOP
}

// ---------------- LayerNorm (fp16 output) ----------------
__global__ __launch_bounds__(256) void ln_kernel(
    const float* __restrict__ x, const float* __restrict__ g,
    const float* __restrict__ b, __half* __restrict__ out)
{
    int row = blockIdx.x;
    int tid = threadIdx.x;
    const float* xr = x + (size_t)row * DM;
    float4 xv = reinterpret_cast<const float4*>(xr)[tid];
    float s  = xv.x + xv.y + xv.z + xv.w;
    float sq = xv.x*xv.x + xv.y*xv.y + xv.z*xv.z + xv.w*xv.w;

    __shared__ float sh1[256], sh2[256];
    sh1[tid] = s; sh2[tid] = sq;
    __syncthreads();
    #pragma unroll
    for (int o = 128; o > 0; o >>= 1) {
        if (tid < o) { sh1[tid] += sh1[tid + o]; sh2[tid] += sh2[tid + o]; }
        __syncthreads();
    }
    float mu   = sh1[0] * (1.0f / DM);
    float var  = sh2[0] * (1.0f / DM) - mu * mu;
    float rstd = rsqrtf(var + 1e-5f);

    float4 gv = reinterpret_cast<const float4*>(g)[tid];
    float4 bv = reinterpret_cast<const float4*>(b)[tid];
    __half2 lo = __floats2half2_rn((xv.x - mu) * rstd * gv.x + bv.x,
                                   (xv.y - mu) * rstd * gv.y + bv.y);
    __half2 hi = __floats2half2_rn((xv.z - mu) * rstd * gv.z + bv.z,
                                   (xv.w - mu) * rstd * gv.w + bv.w);
    reinterpret_cast<uint2*>(out + (size_t)row * DM)[tid] = make_uint2(h2u(lo), h2u(hi));
}

// ---------------- fp16 MMA GEMM: TM x 128 block, 8 warps, BK=32 --------------
#define ASTR 40
#define BSTR 136
#define HBK  32
#define GNST 3

template<int TM, int OP>
__global__ __launch_bounds__(256) void hgemm(
    const __half* __restrict__ A, const __half* __restrict__ B,
    const float* __restrict__ bias, const float* __restrict__ res,
    void* __restrict__ Cv, __half* __restrict__ Qo, __half* __restrict__ Ko,
    __half* __restrict__ Vo, int M, int N, int K)
{
    constexpr int NWN   = (TM == 128) ? 2 : 4;
    constexpr int NT    = 16 / NWN;
    constexpr int STAGE = TM * ASTR + HBK * BSTR;

    extern __shared__ __half sh[];

    const int tid  = threadIdx.x;
    const int lane = tid & 31;
    const int warp = tid >> 5;
    const int g    = lane >> 2;
    const int tig  = lane & 3;
    const int wm   = warp / NWN;
    const int wn   = warp % NWN;
    const int m0   = blockIdx.x * TM;
    const int n0   = blockIdx.y * 128;

    const int lt = lane >> 3;
    const int li = lane & 7;
    const int arow_l = wm * 32 + (lt & 1) * 8 + li;
    const int acol_l = (lt >> 1) * 8;
    const int brow_l = (lt & 1) * 8 + li;
    const int bcol_l = wn * (NT * 8) + (lt >> 1) * 8;

    float acc[2][NT][4];
    #pragma unroll
    for (int mt = 0; mt < 2; mt++)
        #pragma unroll
        for (int nt = 0; nt < NT; nt++)
            #pragma unroll
            for (int i = 0; i < 4; i++) acc[mt][nt][i] = 0.0f;

    const int nsteps = K >> 5;

    #define LOAD_STAGE(sp, kt) do { \
        __half* As = sh + (sp) * STAGE; \
        __half* Bs = As + TM * ASTR; \
        _Pragma("unroll") \
        for (int t = 0; t < TM / 64; t++) { \
            int idx = t * 256 + tid; \
            int arw = idx >> 2, aof = (idx & 3) * 8; \
            cp16(&As[arw * ASTR + aof], A + (size_t)(m0 + arw) * K + (kt) + aof); \
        } \
        _Pragma("unroll") \
        for (int t = 0; t < 2; t++) { \
            int idx = t * 256 + tid; \
            int brw = idx >> 4, bof = (idx & 15) * 8; \
            cp16(&Bs[brw * BSTR + bof], B + (size_t)((kt) + brw) * N + n0 + bof); \
        } \
        asm volatile("cp.async.commit_group;\n"); \
    } while (0)

    #pragma unroll
    for (int s = 0; s < GNST - 1; s++) LOAD_STAGE(s, s * HBK);

    for (int it = 0; it < nsteps; it++) {
        asm volatile("cp.async.wait_group %0;\n" :: "n"(GNST - 2));
        __syncthreads();

        if (it + GNST - 1 < nsteps)
            LOAD_STAGE((it + GNST - 1) % GNST, (it + GNST - 1) * HBK);
        else
            asm volatile("cp.async.commit_group;\n");

        const __half* As = sh + (it % GNST) * STAGE;
        const __half* Bs = As + TM * ASTR;

        #pragma unroll
        for (int kb = 0; kb < HBK; kb += 16) {
            unsigned a[2][4], b[NT][2];
            ldsm4(a[0], &As[arow_l * ASTR + kb + acol_l]);
            ldsm4(a[1], &As[(arow_l + 16) * ASTR + kb + acol_l]);
            #pragma unroll
            for (int ntp = 0; ntp < NT / 2; ntp++) {
                unsigned t4[4];
                ldsm4t(t4, &Bs[(kb + brow_l) * BSTR + bcol_l + ntp * 16]);
                b[2 * ntp][0]     = t4[0]; b[2 * ntp][1]     = t4[1];
                b[2 * ntp + 1][0] = t4[2]; b[2 * ntp + 1][1] = t4[3];
            }
            #pragma unroll
            for (int mt = 0; mt < 2; mt++)
                #pragma unroll
                for (int nt = 0; nt < NT; nt++)
                    mma16(acc[mt][nt], a[mt], b[nt]);
        }
    }
    #undef LOAD_STAGE

    if (OP == 3) {
        const int grp = (n0 >> 6) + wn;
        const int cls = grp >> 4;
        const int hh  = grp & 15;
        __half* Dst = (cls == 0) ? Qo : (cls == 1) ? Ko : Vo;

        #pragma unroll
        for (int mt = 0; mt < 2; mt++) {
            const int r0 = m0 + wm * 32 + mt * 16 + g;
            const int r1 = r0 + 8;
            float v[NT][4];
            float ss0 = 0.0f, ss1 = 0.0f;
            #pragma unroll
            for (int nt = 0; nt < NT; nt++) {
                const int c = n0 + wn * (NT * 8) + nt * 8 + tig * 2;
                const float b0 = bias[c], b1 = bias[c + 1];
                v[nt][0] = acc[mt][nt][0] + b0;
                v[nt][1] = acc[mt][nt][1] + b1;
                v[nt][2] = acc[mt][nt][2] + b0;
                v[nt][3] = acc[mt][nt][3] + b1;
                ss0 += v[nt][0] * v[nt][0] + v[nt][1] * v[nt][1];
                ss1 += v[nt][2] * v[nt][2] + v[nt][3] * v[nt][3];
            }
            ss0 += __shfl_xor_sync(0xffffffffu, ss0, 1);
            ss0 += __shfl_xor_sync(0xffffffffu, ss0, 2);
            ss1 += __shfl_xor_sync(0xffffffffu, ss1, 1);
            ss1 += __shfl_xor_sync(0xffffffffu, ss1, 2);
            float sc0 = 1.0f, sc1 = 1.0f;
            if (cls == 0) {
                sc0 = 0.125f / fmaxf(sqrtf(ss0), 1e-12f);
                sc1 = 0.125f / fmaxf(sqrtf(ss1), 1e-12f);
            } else if (cls == 1) {
                sc0 = 1.0f / fmaxf(sqrtf(ss0), 1e-12f);
                sc1 = 1.0f / fmaxf(sqrtf(ss1), 1e-12f);
            }
            __half* d0p = Dst + ((size_t)hh * SEQ + r0) * HD + tig * 2;
            __half* d1p = Dst + ((size_t)hh * SEQ + r1) * HD + tig * 2;
            #pragma unroll
            for (int nt = 0; nt < NT; nt++) {
                *reinterpret_cast<unsigned*>(d0p + nt * 8) =
                    h2u(__floats2half2_rn(v[nt][0] * sc0, v[nt][1] * sc0));
                *reinterpret_cast<unsigned*>(d1p + nt * 8) =
                    h2u(__floats2half2_rn(v[nt][2] * sc1, v[nt][3] * sc1));
            }
        }
        return;
    }

    #pragma unroll
    for (int mt = 0; mt < 2; mt++) {
        const int r0 = m0 + wm * 32 + mt * 16 + g;
        const int r1 = r0 + 8;
        #pragma unroll
        for (int nt = 0; nt < NT; nt++) {
            const int c = n0 + wn * (NT * 8) + nt * 8 + tig * 2;
            const float b0 = bias[c], b1 = bias[c + 1];
            float v0 = acc[mt][nt][0] + b0;
            float v1 = acc[mt][nt][1] + b1;
            float v2 = acc[mt][nt][2] + b0;
            float v3 = acc[mt][nt][3] + b1;
            if (OP == 1) {
                float* Cf = (float*)Cv;
                const float2 ra = *reinterpret_cast<const float2*>(res + (size_t)r0 * N + c);
                const float2 rb = *reinterpret_cast<const float2*>(res + (size_t)r1 * N + c);
                *reinterpret_cast<float2*>(Cf + (size_t)r0 * N + c) = make_float2(v0 + ra.x, v1 + ra.y);
                *reinterpret_cast<float2*>(Cf + (size_t)r1 * N + c) = make_float2(v2 + rb.x, v3 + rb.y);
            } else {
                if (OP == 2) {
                    v0 = 0.5f * v0 * (1.0f + erff(v0 * 0.70710678118654752f));
                    v1 = 0.5f * v1 * (1.0f + erff(v1 * 0.70710678118654752f));
                    v2 = 0.5f * v2 * (1.0f + erff(v2 * 0.70710678118654752f));
                    v3 = 0.5f * v3 * (1.0f + erff(v3 * 0.70710678118654752f));
                }
                __half* Ch = (__half*)Cv;
                *reinterpret_cast<unsigned*>(Ch + (size_t)r0 * N + c) = h2u(__floats2half2_rn(v0, v1));
                *reinterpret_cast<unsigned*>(Ch + (size_t)r1 * N + c) = h2u(__floats2half2_rn(v2, v3));
            }
        }
    }
}

// ---------------- fp16 MMA attention: 64-query blocks, 4 warps ---------------
// fp16-accum S-MMA (c-frag == P a-frag, no CVTs); ones-MMA denominator;
// Q staged through K buffer (no separate Q smem) -> 36.9KB/CTA, more CTAs/SM.
#define QSTR 72
#define KVSTAGE (64 * QSTR)
__global__ __launch_bounds__(128) void attn_h_kernel(
    const __half* __restrict__ Q, const __half* __restrict__ Km,
    const __half* __restrict__ V, const float* __restrict__ lcc,
    __half* __restrict__ out)
{
    extern __shared__ __half apool[];
    __half* Kb = apool;                   // [2][64][QSTR]
    __half* Vb = apool + 2 * KVSTAGE;     // [2][64][QSTR]
    __shared__ __half2 lccs[2][32];

    const int h    = blockIdx.y;
    const int m0   = blockIdx.x * 64;
    const int tid  = threadIdx.x;
    const int lane = tid & 31;
    const int warp = tid >> 5;
    const int g    = lane >> 2;
    const int tig  = lane & 3;
    const int lt   = lane >> 3;
    const int li   = lane & 7;

    const int kb_n = ((lane >> 4) << 3) + li;
    const int kb_k = ((lane >> 3) & 1) * 8;

    const __half* Kg = Km + (size_t)h * SEQ * HD;
    const __half* Vg = V  + (size_t)h * SEQ * HD;

    // ---- stage Q through Kb, extract fragments, then free the buffer ----
    {
        const __half* Qg = Q + ((size_t)h * SEQ + m0) * HD;
        #pragma unroll
        for (int t = 0; t < 4; t++) {
            int idx = t * 128 + tid;
            int row = idx >> 3;
            int off = (idx & 7) * 8;
            *reinterpret_cast<uint4*>(&Kb[row * QSTR + off]) =
                *reinterpret_cast<const uint4*>(Qg + (size_t)row * HD + off);
        }
    }
    __syncthreads();

    unsigned qa[4][4];
    {
        const int qrow = warp * 16 + (lt & 1) * 8 + li;
        const int qcol = (lt >> 1) * 8;
        #pragma unroll
        for (int kc = 0; kc < 4; kc++)
            ldsm4(qa[kc], &Kb[qrow * QSTR + kc * 16 + qcol]);
    }
    __syncthreads();   // all warps done reading Q before Kb is overwritten

    #define LOAD_KV(sb, kt) do { \
        __half* Kd = Kb + (sb) * KVSTAGE; \
        __half* Vd = Vb + (sb) * KVSTAGE; \
        _Pragma("unroll") \
        for (int t = 0; t < 4; t++) { \
            int idx = t * 128 + tid; \
            int row = idx >> 3; \
            int off = (idx & 7) * 8; \
            cp16(&Kd[row * QSTR + off], Kg + (size_t)((kt) + row) * HD + off); \
            cp16(&Vd[row * QSTR + off], Vg + (size_t)((kt) + row) * HD + off); \
        } \
        asm volatile("cp.async.commit_group;\n"); \
        if (tid < 32) { \
            float e0 = __expf(lcc[(kt) + 2 * tid]     * 0.05f); \
            float e1 = __expf(lcc[(kt) + 2 * tid + 1] * 0.05f); \
            lccs[sb][tid] = __floats2half2_rn(e0, e1); \
        } \
    } while (0)

    LOAD_KV(0, 0);

    float o[8][4];
    #pragma unroll
    for (int nt = 0; nt < 8; nt++)
        #pragma unroll
        for (int i = 0; i < 4; i++) o[nt][i] = 0.0f;
    float dacc[4] = {0.0f, 0.0f, 0.0f, 0.0f};
    const unsigned ones2 = h2u(__floats2half2_rn(1.0f, 1.0f));
    const unsigned b_ones[2] = {ones2, ones2};

    for (int ti = 0; ti < SEQ / 64; ti++) {
        const int buf = ti & 1;
        __syncthreads();
        if (ti + 1 < SEQ / 64) {
            LOAD_KV(buf ^ 1, (ti + 1) * 64);
        } else {
            asm volatile("cp.async.commit_group;\n");
        }
        asm volatile("cp.async.wait_group 1;\n");
        __syncthreads();

        const __half* Ks = Kb + buf * KVSTAGE;
        const __half* Vs = Vb + buf * KVSTAGE;

        // ---- S = Q @ K^T with fp16 accumulation (packed half2 c-frags) ----
        unsigned s2[8][2];
        #pragma unroll
        for (int nt = 0; nt < 8; nt++) { s2[nt][0] = 0u; s2[nt][1] = 0u; }

        #pragma unroll
        for (int kc = 0; kc < 4; kc++) {
            #pragma unroll
            for (int ng = 0; ng < 4; ng++) {
                unsigned t4[4];
                ldsm4(t4, &Ks[(ng * 16 + kb_n) * QSTR + kc * 16 + kb_k]);
                mma16h(s2[2 * ng],     qa[kc], t4);
                mma16h(s2[2 * ng + 1], qa[kc], t4 + 2);
            }
        }

        // ---- softmax numerators in-place: p = h2exp(s) * E_c ----
        #pragma unroll
        for (int nt = 0; nt < 8; nt++) {
            __half2 ec = lccs[buf][nt * 4 + tig];
            s2[nt][0] = h2u(__hmul2(h2exp(u2h(s2[nt][0])), ec));
            s2[nt][1] = h2u(__hmul2(h2exp(u2h(s2[nt][1])), ec));
        }

        // ---- O += P @ V; denominator via ones-column MMA ----
        #pragma unroll
        for (int kc = 0; kc < 4; kc++) {
            unsigned a[4];
            a[0] = s2[2 * kc][0];
            a[1] = s2[2 * kc][1];
            a[2] = s2[2 * kc + 1][0];
            a[3] = s2[2 * kc + 1][1];
            mma16(dacc, a, b_ones);
            unsigned vb[8][2];
            #pragma unroll
            for (int ntp = 0; ntp < 4; ntp++) {
                unsigned t4[4];
                ldsm4t(t4, &Vs[(kc * 16 + (lt & 1) * 8 + li) * QSTR + (ntp * 2 + (lt >> 1)) * 8]);
                vb[2 * ntp][0]     = t4[0]; vb[2 * ntp][1]     = t4[1];
                vb[2 * ntp + 1][0] = t4[2]; vb[2 * ntp + 1][1] = t4[3];
            }
            #pragma unroll
            for (int nt = 0; nt < 8; nt++)
                mma16(o[nt], a, vb[nt]);
        }
    }
    #undef LOAD_KV

    const float inv0 = 1.0f / dacc[0];
    const float inv1 = 1.0f / dacc[2];

    const int r0 = m0 + warp * 16 + g;
    const int r1 = r0 + 8;
    #pragma unroll
    for (int nt = 0; nt < 8; nt++) {
        const int c = h * HD + nt * 8 + tig * 2;
        *reinterpret_cast<unsigned*>(out + (size_t)r0 * DM + c) =
            h2u(__floats2half2_rn(o[nt][0] * inv0, o[nt][1] * inv0));
        *reinterpret_cast<unsigned*>(out + (size_t)r1 * DM + c) =
            h2u(__floats2half2_rn(o[nt][2] * inv1, o[nt][3] * inv1));
    }
}

// ---------------- launch --------------------------------------------------------
extern "C" void kernel_launch(void* const* d_in, const int* in_sizes, int n_in,
                              void* d_out, int out_size)
{
    const float* x     = (const float*)d_in[0];
    const float* lcc   = (const float*)d_in[1];
    const float* w_qkv = (const float*)d_in[2];
    const float* b_qkv = (const float*)d_in[3];
    const float* w_out = (const float*)d_in[4];
    const float* b_out = (const float*)d_in[5];
    const float* ln1_g = (const float*)d_in[6];
    const float* ln1_b = (const float*)d_in[7];
    const float* ln2_g = (const float*)d_in[8];
    const float* ln2_b = (const float*)d_in[9];
    const float* w_ff1 = (const float*)d_in[10];
    const float* b_ff1 = (const float*)d_in[11];
    const float* w_ff2 = (const float*)d_in[12];
    const float* b_ff2 = (const float*)d_in[13];
    float* out = (float*)d_out;

    __half *normed, *q, *k, *v, *attn, *normed2, *ffh;
    __half *wqkv_h, *wout_h, *wff1_h, *wff2_h;
    float *x2;
    cudaGetSymbolAddress((void**)&normed,  g_normed);
    cudaGetSymbolAddress((void**)&q,       g_q);
    cudaGetSymbolAddress((void**)&k,       g_k);
    cudaGetSymbolAddress((void**)&v,       g_v);
    cudaGetSymbolAddress((void**)&attn,    g_attn);
    cudaGetSymbolAddress((void**)&x2,      g_x2);
    cudaGetSymbolAddress((void**)&normed2, g_normed2);
    cudaGetSymbolAddress((void**)&ffh,     g_ffh);
    cudaGetSymbolAddress((void**)&wqkv_h,  g_wqkv_h);
    cudaGetSymbolAddress((void**)&wout_h,  g_wout_h);
    cudaGetSymbolAddress((void**)&wff1_h,  g_wff1_h);
    cudaGetSymbolAddress((void**)&wff2_h,  g_wff2_h);

    const int smem128 = GNST * (128 * ASTR + HBK * BSTR) * 2;
    const int smem64  = GNST * (64 * ASTR + HBK * BSTR) * 2;
    cudaFuncSetAttribute((const void*)hgemm<128,3>, cudaFuncAttributeMaxDynamicSharedMemorySize, smem128);
    cudaFuncSetAttribute((const void*)hgemm<128,2>, cudaFuncAttributeMaxDynamicSharedMemorySize, smem128);
    cudaFuncSetAttribute((const void*)hgemm<64,1>,  cudaFuncAttributeMaxDynamicSharedMemorySize, smem64);

    const int asmem = 4 * KVSTAGE * 2;   // 36,864 B
    cudaFuncSetAttribute(attn_h_kernel, cudaFuncAttributeMaxDynamicSharedMemorySize, asmem);

    // 0+1. fused: LN1 (blocks 0..2047) + weight convert (remaining blocks)
    ln_cvt_kernel<<<SEQ + 1184, 256>>>(
        x, ln1_g, ln1_b, normed,
        w_qkv, wqkv_h, DM * 3 * DM / 4,
        w_out, wout_h, DM * DM / 4,
        w_ff1, wff1_h, DM * DFF / 4,
        w_ff2, wff2_h, DFF * DM / 4);

    // 2. QKV projection + fused split/cosine-normalize/relayout
    hgemm<128,3><<<dim3(SEQ / 128, 3 * DM / 128), 256, smem128>>>(
        normed, wqkv_h, b_qkv, nullptr, nullptr, q, k, v, SEQ, 3 * DM, DM);
    // 3. attention (fp16 MMA, 64-row blocks)
    attn_h_kernel<<<dim3(SEQ / 64, NH), 128, asmem>>>(q, k, v, lcc, attn);
    // 4. out projection + residual (fp32 out) — 64-row tiles
    hgemm<64,1><<<dim3(SEQ / 64, DM / 128), 256, smem64>>>(
        attn, wout_h, b_out, x, x2, nullptr, nullptr, nullptr, SEQ, DM, DM);
    // 5. LN2 (fp16 output)
    ln_kernel<<<SEQ, 256>>>(x2, ln2_g, ln2_b, normed2);
    // 6. FF1 + exact GELU (fp16 output)
    hgemm<128,2><<<dim3(SEQ / 128, DFF / 128), 256, smem128>>>(
        normed2, wff1_h, b_ff1, nullptr, ffh, nullptr, nullptr, nullptr, SEQ, DFF, DM);
    // 7. FF2 + residual -> out (fp32) — 64-row tiles
    hgemm<64,1><<<dim3(SEQ / 64, DM / 128), 256, smem64>>>(
        ffh, wff2_h, b_ff2, x2, out, nullptr, nullptr, nullptr, SEQ, DM, DFF);
}

// round 16
// speedup vs baseline: 1.0319x; 1.0251x over previous
#include <cuda_runtime.h>
#include <cuda_fp16.h>
#include <cstdint>
#include <math.h>

#define SEQ  2048
#define DM   1024
#define NH   16
#define HD   64
#define DFF  4096

// ---------------- scratch (no allocation allowed) ----------------
__device__ __half g_normed [SEQ * DM];
__device__ __half g_q      [NH * SEQ * HD];
__device__ __half g_k      [NH * SEQ * HD];
__device__ __half g_v      [NH * SEQ * HD];
__device__ __half g_attn   [SEQ * DM];
__device__ float  g_x2     [SEQ * DM];
__device__ __half g_normed2[SEQ * DM];
__device__ __half g_ffh    [SEQ * DFF];
// fp16 weight copies
__device__ __half g_wqkv_h [DM * 3 * DM];
__device__ __half g_wout_h [DM * DM];
__device__ __half g_wff1_h [DM * DFF];
__device__ __half g_wff2_h [DFF * DM];

// ---------------- helpers ----------------
__device__ __forceinline__ unsigned h2u(__half2 h) { return *reinterpret_cast<unsigned*>(&h); }
__device__ __forceinline__ __half2 u2h(unsigned u) { return *reinterpret_cast<__half2*>(&u); }

__device__ __forceinline__ void mma16(float* d, const unsigned* a, const unsigned* b) {
    asm volatile(
        "mma.sync.aligned.m16n8k16.row.col.f32.f16.f16.f32 "
        "{%0,%1,%2,%3}, {%4,%5,%6,%7}, {%8,%9}, {%0,%1,%2,%3};\n"
        : "+f"(d[0]), "+f"(d[1]), "+f"(d[2]), "+f"(d[3])
        : "r"(a[0]), "r"(a[1]), "r"(a[2]), "r"(a[3]), "r"(b[0]), "r"(b[1]));
}
__device__ __forceinline__ void mma16h(unsigned* d, const unsigned* a, const unsigned* b) {
    asm volatile(
        "mma.sync.aligned.m16n8k16.row.col.f16.f16.f16.f16 "
        "{%0,%1}, {%2,%3,%4,%5}, {%6,%7}, {%0,%1};\n"
        : "+r"(d[0]), "+r"(d[1])
        : "r"(a[0]), "r"(a[1]), "r"(a[2]), "r"(a[3]), "r"(b[0]), "r"(b[1]));
}
__device__ __forceinline__ void cp16(void* sdst, const void* gsrc) {
    unsigned int d = (unsigned int)__cvta_generic_to_shared(sdst);
    asm volatile("cp.async.cg.shared.global [%0], [%1], 16;\n" :: "r"(d), "l"(gsrc));
}
__device__ __forceinline__ void ldsm4(unsigned* r, const void* saddr) {
    unsigned int ad = (unsigned int)__cvta_generic_to_shared(saddr);
    asm volatile("ldmatrix.sync.aligned.m8n8.x4.shared.b16 {%0,%1,%2,%3}, [%4];\n"
        : "=r"(r[0]), "=r"(r[1]), "=r"(r[2]), "=r"(r[3]) : "r"(ad));
}
__device__ __forceinline__ void ldsm4t(unsigned* r, const void* saddr) {
    unsigned int ad = (unsigned int)__cvta_generic_to_shared(saddr);
    asm volatile("ldmatrix.sync.aligned.m8n8.x4.trans.shared.b16 {%0,%1,%2,%3}, [%4];\n"
        : "=r"(r[0]), "=r"(r[1]), "=r"(r[2]), "=r"(r[3]) : "r"(ad));
}

// ---------------- fused LN1 + weight convert (one launch) ----------
__global__ __launch_bounds__(256) void ln_cvt_kernel(
    const float* __restrict__ x, const float* __restrict__ g,
    const float* __restrict__ b, __half* __restrict__ out,
    const float* __restrict__ s0, __half* __restrict__ d0, int n0,
    const float* __restrict__ s1, __half* __restrict__ d1, int n1,
    const float* __restrict__ s2, __half* __restrict__ d2, int n2,
    const float* __restrict__ s3, __half* __restrict__ d3, int n3)
{
    int tid = threadIdx.x;
    if (blockIdx.x < SEQ) {
        int row = blockIdx.x;
        const float* xr = x + (size_t)row * DM;
        float4 xv = reinterpret_cast<const float4*>(xr)[tid];
        float s  = xv.x + xv.y + xv.z + xv.w;
        float sq = xv.x*xv.x + xv.y*xv.y + xv.z*xv.z + xv.w*xv.w;

        __shared__ float sh1[256], sh2[256];
        sh1[tid] = s; sh2[tid] = sq;
        __syncthreads();
        #pragma unroll
        for (int o = 128; o > 0; o >>= 1) {
            if (tid < o) { sh1[tid] += sh1[tid + o]; sh2[tid] += sh2[tid + o]; }
            __syncthreads();
        }
        float mu   = sh1[0] * (1.0f / DM);
        float var  = sh2[0] * (1.0f / DM) - mu * mu;
        float rstd = rsqrtf(var + 1e-5f);

        float4 gv = reinterpret_cast<const float4*>(g)[tid];
        float4 bv = reinterpret_cast<const float4*>(b)[tid];
        __half2 lo = __floats2half2_rn((xv.x - mu) * rstd * gv.x + bv.x,
                                       (xv.y - mu) * rstd * gv.y + bv.y);
        __half2 hi = __floats2half2_rn((xv.z - mu) * rstd * gv.z + bv.z,
                                       (xv.w - mu) * rstd * gv.w + bv.w);
        reinterpret_cast<uint2*>(out + (size_t)row * DM)[tid] = make_uint2(h2u(lo), h2u(hi));
        return;
    }
    int i = (blockIdx.x - SEQ) * blockDim.x + tid;
    int stride = (gridDim.x - SEQ) * blockDim.x;
    #define CVT_LOOP(S, D, N) \
    for (int j = i; j < N; j += stride) { \
        float4 v = reinterpret_cast<const float4*>(S)[j]; \
        __half2 lo = __floats2half2_rn(v.x, v.y); \
        __half2 hi = __floats2half2_rn(v.z, v.w); \
        reinterpret_cast<uint2*>(D)[j] = make_uint2(h2u(lo), h2u(hi)); \
    }
    CVT_LOOP(s0, d0, n0) CVT_LOOP(s1, d1, n1) CVT_LOOP(s2, d2, n2) CVT_LOOP(s3, d3, n3)
    #undef CVT_LOOP
}

// ---------------- LayerNorm (fp16 output) ----------------
__global__ __launch_bounds__(256) void ln_kernel(
    const float* __restrict__ x, const float* __restrict__ g,
    const float* __restrict__ b, __half* __restrict__ out)
{
    int row = blockIdx.x;
    int tid = threadIdx.x;
    const float* xr = x + (size_t)row * DM;
    float4 xv = reinterpret_cast<const float4*>(xr)[tid];
    float s  = xv.x + xv.y + xv.z + xv.w;
    float sq = xv.x*xv.x + xv.y*xv.y + xv.z*xv.z + xv.w*xv.w;

    __shared__ float sh1[256], sh2[256];
    sh1[tid] = s; sh2[tid] = sq;
    __syncthreads();
    #pragma unroll
    for (int o = 128; o > 0; o >>= 1) {
        if (tid < o) { sh1[tid] += sh1[tid + o]; sh2[tid] += sh2[tid + o]; }
        __syncthreads();
    }
    float mu   = sh1[0] * (1.0f / DM);
    float var  = sh2[0] * (1.0f / DM) - mu * mu;
    float rstd = rsqrtf(var + 1e-5f);

    float4 gv = reinterpret_cast<const float4*>(g)[tid];
    float4 bv = reinterpret_cast<const float4*>(b)[tid];
    __half2 lo = __floats2half2_rn((xv.x - mu) * rstd * gv.x + bv.x,
                                   (xv.y - mu) * rstd * gv.y + bv.y);
    __half2 hi = __floats2half2_rn((xv.z - mu) * rstd * gv.z + bv.z,
                                   (xv.w - mu) * rstd * gv.w + bv.w);
    reinterpret_cast<uint2*>(out + (size_t)row * DM)[tid] = make_uint2(h2u(lo), h2u(hi));
}

// ---------------- fp16 MMA GEMM: 64 x TN blocks, 128 threads (2x2 warps) -----
// OP = 1: float C = A*B + bias + res; OP = 2: half C = gelu(A*B + bias)
// OP = 3: QKV epilogue (TN=128) — L2-normalize q,k; write [H,L,64] layout
#define ASTR 40
#define HBK  32
#define GNST 3

template<int TN, int OP>
__global__ __launch_bounds__(128) void hgemm64(
    const __half* __restrict__ A, const __half* __restrict__ B,
    const float* __restrict__ bias, const float* __restrict__ res,
    void* __restrict__ Cv, __half* __restrict__ Qo, __half* __restrict__ Ko,
    __half* __restrict__ Vo, int M, int N, int K)
{
    constexpr int NT    = TN / 16;             // n-tiles (8-col) per warp
    constexpr int BSTR2 = TN + 8;
    constexpr int STAGE = 64 * ASTR + HBK * BSTR2;
    constexpr int BCH   = TN / 8;              // cp16 chunks per B row

    extern __shared__ __half sh[];

    const int tid  = threadIdx.x;
    const int lane = tid & 31;
    const int warp = tid >> 5;
    const int g    = lane >> 2;
    const int tig  = lane & 3;
    const int wm   = warp >> 1;                // 0..1
    const int wn   = warp & 1;                 // 0..1
    const int m0   = blockIdx.x * 64;
    const int n0   = blockIdx.y * TN;

    const int lt = lane >> 3;
    const int li = lane & 7;
    const int arow_l = wm * 32 + (lt & 1) * 8 + li;
    const int acol_l = (lt >> 1) * 8;
    const int brow_l = (lt & 1) * 8 + li;
    const int bcol_l = wn * (NT * 8) + (lt >> 1) * 8;

    float acc[2][NT][4];
    #pragma unroll
    for (int mt = 0; mt < 2; mt++)
        #pragma unroll
        for (int nt = 0; nt < NT; nt++)
            #pragma unroll
            for (int i = 0; i < 4; i++) acc[mt][nt][i] = 0.0f;

    const int nsteps = K >> 5;

    #define LOAD_STAGE(sp, kt) do { \
        __half* As = sh + (sp) * STAGE; \
        __half* Bs = As + 64 * ASTR; \
        _Pragma("unroll") \
        for (int t = 0; t < 2; t++) { \
            int idx = t * 128 + tid; \
            int arw = idx >> 2, aof = (idx & 3) * 8; \
            cp16(&As[arw * ASTR + aof], A + (size_t)(m0 + arw) * K + (kt) + aof); \
        } \
        _Pragma("unroll") \
        for (int t = 0; t < TN / 32; t++) { \
            int idx = t * 128 + tid; \
            int brw = idx / BCH, bof = (idx % BCH) * 8; \
            cp16(&Bs[brw * BSTR2 + bof], B + (size_t)((kt) + brw) * N + n0 + bof); \
        } \
        asm volatile("cp.async.commit_group;\n"); \
    } while (0)

    #pragma unroll
    for (int s = 0; s < GNST - 1; s++) LOAD_STAGE(s, s * HBK);

    for (int it = 0; it < nsteps; it++) {
        asm volatile("cp.async.wait_group %0;\n" :: "n"(GNST - 2));
        __syncthreads();

        if (it + GNST - 1 < nsteps)
            LOAD_STAGE((it + GNST - 1) % GNST, (it + GNST - 1) * HBK);
        else
            asm volatile("cp.async.commit_group;\n");

        const __half* As = sh + (it % GNST) * STAGE;
        const __half* Bs = As + 64 * ASTR;

        #pragma unroll
        for (int kb = 0; kb < HBK; kb += 16) {
            unsigned a[2][4], b[NT][2];
            ldsm4(a[0], &As[arow_l * ASTR + kb + acol_l]);
            ldsm4(a[1], &As[(arow_l + 16) * ASTR + kb + acol_l]);
            #pragma unroll
            for (int ntp = 0; ntp < NT / 2; ntp++) {
                unsigned t4[4];
                ldsm4t(t4, &Bs[(kb + brow_l) * BSTR2 + bcol_l + ntp * 16]);
                b[2 * ntp][0]     = t4[0]; b[2 * ntp][1]     = t4[1];
                b[2 * ntp + 1][0] = t4[2]; b[2 * ntp + 1][1] = t4[3];
            }
            #pragma unroll
            for (int mt = 0; mt < 2; mt++)
                #pragma unroll
                for (int nt = 0; nt < NT; nt++)
                    mma16(acc[mt][nt], a[mt], b[nt]);
        }
    }
    #undef LOAD_STAGE

    // ---------------- epilogue ----------------
    if (OP == 3) {
        const int grp = (n0 >> 6) + wn;     // 0..47
        const int cls = grp >> 4;           // 0=q, 1=k, 2=v
        const int hh  = grp & 15;
        __half* Dst = (cls == 0) ? Qo : (cls == 1) ? Ko : Vo;

        #pragma unroll
        for (int mt = 0; mt < 2; mt++) {
            const int r0 = m0 + wm * 32 + mt * 16 + g;
            const int r1 = r0 + 8;
            float v[NT][4];
            float ss0 = 0.0f, ss1 = 0.0f;
            #pragma unroll
            for (int nt = 0; nt < NT; nt++) {
                const int c = n0 + wn * (NT * 8) + nt * 8 + tig * 2;
                const float b0 = bias[c], b1 = bias[c + 1];
                v[nt][0] = acc[mt][nt][0] + b0;
                v[nt][1] = acc[mt][nt][1] + b1;
                v[nt][2] = acc[mt][nt][2] + b0;
                v[nt][3] = acc[mt][nt][3] + b1;
                ss0 += v[nt][0] * v[nt][0] + v[nt][1] * v[nt][1];
                ss1 += v[nt][2] * v[nt][2] + v[nt][3] * v[nt][3];
            }
            ss0 += __shfl_xor_sync(0xffffffffu, ss0, 1);
            ss0 += __shfl_xor_sync(0xffffffffu, ss0, 2);
            ss1 += __shfl_xor_sync(0xffffffffu, ss1, 1);
            ss1 += __shfl_xor_sync(0xffffffffu, ss1, 2);
            float sc0 = 1.0f, sc1 = 1.0f;
            if (cls == 0) {
                sc0 = 0.125f / fmaxf(sqrtf(ss0), 1e-12f);
                sc1 = 0.125f / fmaxf(sqrtf(ss1), 1e-12f);
            } else if (cls == 1) {
                sc0 = 1.0f / fmaxf(sqrtf(ss0), 1e-12f);
                sc1 = 1.0f / fmaxf(sqrtf(ss1), 1e-12f);
            }
            __half* d0p = Dst + ((size_t)hh * SEQ + r0) * HD + tig * 2;
            __half* d1p = Dst + ((size_t)hh * SEQ + r1) * HD + tig * 2;
            #pragma unroll
            for (int nt = 0; nt < NT; nt++) {
                *reinterpret_cast<unsigned*>(d0p + nt * 8) =
                    h2u(__floats2half2_rn(v[nt][0] * sc0, v[nt][1] * sc0));
                *reinterpret_cast<unsigned*>(d1p + nt * 8) =
                    h2u(__floats2half2_rn(v[nt][2] * sc1, v[nt][3] * sc1));
            }
        }
        return;
    }

    #pragma unroll
    for (int mt = 0; mt < 2; mt++) {
        const int r0 = m0 + wm * 32 + mt * 16 + g;
        const int r1 = r0 + 8;
        #pragma unroll
        for (int nt = 0; nt < NT; nt++) {
            const int c = n0 + wn * (NT * 8) + nt * 8 + tig * 2;
            const float b0 = bias[c], b1 = bias[c + 1];
            float v0 = acc[mt][nt][0] + b0;
            float v1 = acc[mt][nt][1] + b1;
            float v2 = acc[mt][nt][2] + b0;
            float v3 = acc[mt][nt][3] + b1;
            if (OP == 1) {
                float* Cf = (float*)Cv;
                const float2 ra = *reinterpret_cast<const float2*>(res + (size_t)r0 * N + c);
                const float2 rb = *reinterpret_cast<const float2*>(res + (size_t)r1 * N + c);
                *reinterpret_cast<float2*>(Cf + (size_t)r0 * N + c) = make_float2(v0 + ra.x, v1 + ra.y);
                *reinterpret_cast<float2*>(Cf + (size_t)r1 * N + c) = make_float2(v2 + rb.x, v3 + rb.y);
            } else {
                if (OP == 2) {
                    v0 = 0.5f * v0 * (1.0f + erff(v0 * 0.70710678118654752f));
                    v1 = 0.5f * v1 * (1.0f + erff(v1 * 0.70710678118654752f));
                    v2 = 0.5f * v2 * (1.0f + erff(v2 * 0.70710678118654752f));
                    v3 = 0.5f * v3 * (1.0f + erff(v3 * 0.70710678118654752f));
                }
                __half* Ch = (__half*)Cv;
                *reinterpret_cast<unsigned*>(Ch + (size_t)r0 * N + c) = h2u(__floats2half2_rn(v0, v1));
                *reinterpret_cast<unsigned*>(Ch + (size_t)r1 * N + c) = h2u(__floats2half2_rn(v2, v3));
            }
        }
    }
}

// ---------------- fp16 MMA attention: 64-query blocks, 4 warps ---------------
#define QSTR 72
#define KVSTAGE (64 * QSTR)
__global__ __launch_bounds__(128) void attn_h_kernel(
    const __half* __restrict__ Q, const __half* __restrict__ Km,
    const __half* __restrict__ V, const float* __restrict__ lcc,
    __half* __restrict__ out)
{
    extern __shared__ __half apool[];
    __half* Kb = apool;
    __half* Vb = apool + 2 * KVSTAGE;
    __shared__ __half2 lccs[2][32];

    const int h    = blockIdx.y;
    const int m0   = blockIdx.x * 64;
    const int tid  = threadIdx.x;
    const int lane = tid & 31;
    const int warp = tid >> 5;
    const int g    = lane >> 2;
    const int tig  = lane & 3;
    const int lt   = lane >> 3;
    const int li   = lane & 7;

    const int kb_n = ((lane >> 4) << 3) + li;
    const int kb_k = ((lane >> 3) & 1) * 8;

    const __half* Kg = Km + (size_t)h * SEQ * HD;
    const __half* Vg = V  + (size_t)h * SEQ * HD;

    {
        const __half* Qg = Q + ((size_t)h * SEQ + m0) * HD;
        #pragma unroll
        for (int t = 0; t < 4; t++) {
            int idx = t * 128 + tid;
            int row = idx >> 3;
            int off = (idx & 7) * 8;
            *reinterpret_cast<uint4*>(&Kb[row * QSTR + off]) =
                *reinterpret_cast<const uint4*>(Qg + (size_t)row * HD + off);
        }
    }
    __syncthreads();

    unsigned qa[4][4];
    {
        const int qrow = warp * 16 + (lt & 1) * 8 + li;
        const int qcol = (lt >> 1) * 8;
        #pragma unroll
        for (int kc = 0; kc < 4; kc++)
            ldsm4(qa[kc], &Kb[qrow * QSTR + kc * 16 + qcol]);
    }
    __syncthreads();

    #define LOAD_KV(sb, kt) do { \
        __half* Kd = Kb + (sb) * KVSTAGE; \
        __half* Vd = Vb + (sb) * KVSTAGE; \
        _Pragma("unroll") \
        for (int t = 0; t < 4; t++) { \
            int idx = t * 128 + tid; \
            int row = idx >> 3; \
            int off = (idx & 7) * 8; \
            cp16(&Kd[row * QSTR + off], Kg + (size_t)((kt) + row) * HD + off); \
            cp16(&Vd[row * QSTR + off], Vg + (size_t)((kt) + row) * HD + off); \
        } \
        asm volatile("cp.async.commit_group;\n"); \
        if (tid < 32) { \
            float e0 = __expf(lcc[(kt) + 2 * tid]     * 0.05f); \
            float e1 = __expf(lcc[(kt) + 2 * tid + 1] * 0.05f); \
            lccs[sb][tid] = __floats2half2_rn(e0, e1); \
        } \
    } while (0)

    LOAD_KV(0, 0);

    float o[8][4];
    #pragma unroll
    for (int nt = 0; nt < 8; nt++)
        #pragma unroll
        for (int i = 0; i < 4; i++) o[nt][i] = 0.0f;
    float dacc[4] = {0.0f, 0.0f, 0.0f, 0.0f};
    const unsigned ones2 = h2u(__floats2half2_rn(1.0f, 1.0f));
    const unsigned b_ones[2] = {ones2, ones2};

    for (int ti = 0; ti < SEQ / 64; ti++) {
        const int buf = ti & 1;
        __syncthreads();
        if (ti + 1 < SEQ / 64) {
            LOAD_KV(buf ^ 1, (ti + 1) * 64);
        } else {
            asm volatile("cp.async.commit_group;\n");
        }
        asm volatile("cp.async.wait_group 1;\n");
        __syncthreads();

        const __half* Ks = Kb + buf * KVSTAGE;
        const __half* Vs = Vb + buf * KVSTAGE;

        unsigned s2[8][2];
        #pragma unroll
        for (int nt = 0; nt < 8; nt++) { s2[nt][0] = 0u; s2[nt][1] = 0u; }

        #pragma unroll
        for (int kc = 0; kc < 4; kc++) {
            #pragma unroll
            for (int ng = 0; ng < 4; ng++) {
                unsigned t4[4];
                ldsm4(t4, &Ks[(ng * 16 + kb_n) * QSTR + kc * 16 + kb_k]);
                mma16h(s2[2 * ng],     qa[kc], t4);
                mma16h(s2[2 * ng + 1], qa[kc], t4 + 2);
            }
        }

        #pragma unroll
        for (int nt = 0; nt < 8; nt++) {
            __half2 ec = lccs[buf][nt * 4 + tig];
            s2[nt][0] = h2u(__hmul2(h2exp(u2h(s2[nt][0])), ec));
            s2[nt][1] = h2u(__hmul2(h2exp(u2h(s2[nt][1])), ec));
        }

        #pragma unroll
        for (int kc = 0; kc < 4; kc++) {
            unsigned a[4];
            a[0] = s2[2 * kc][0];
            a[1] = s2[2 * kc][1];
            a[2] = s2[2 * kc + 1][0];
            a[3] = s2[2 * kc + 1][1];
            mma16(dacc, a, b_ones);
            unsigned vb[8][2];
            #pragma unroll
            for (int ntp = 0; ntp < 4; ntp++) {
                unsigned t4[4];
                ldsm4t(t4, &Vs[(kc * 16 + (lt & 1) * 8 + li) * QSTR + (ntp * 2 + (lt >> 1)) * 8]);
                vb[2 * ntp][0]     = t4[0]; vb[2 * ntp][1]     = t4[1];
                vb[2 * ntp + 1][0] = t4[2]; vb[2 * ntp + 1][1] = t4[3];
            }
            #pragma unroll
            for (int nt = 0; nt < 8; nt++)
                mma16(o[nt], a, vb[nt]);
        }
    }
    #undef LOAD_KV

    const float inv0 = 1.0f / dacc[0];
    const float inv1 = 1.0f / dacc[2];

    const int r0 = m0 + warp * 16 + g;
    const int r1 = r0 + 8;
    #pragma unroll
    for (int nt = 0; nt < 8; nt++) {
        const int c = h * HD + nt * 8 + tig * 2;
        *reinterpret_cast<unsigned*>(out + (size_t)r0 * DM + c) =
            h2u(__floats2half2_rn(o[nt][0] * inv0, o[nt][1] * inv0));
        *reinterpret_cast<unsigned*>(out + (size_t)r1 * DM + c) =
            h2u(__floats2half2_rn(o[nt][2] * inv1, o[nt][3] * inv1));
    }
}

// ---------------- launch --------------------------------------------------------
extern "C" void kernel_launch(void* const* d_in, const int* in_sizes, int n_in,
                              void* d_out, int out_size)
{
    const float* x     = (const float*)d_in[0];
    const float* lcc   = (const float*)d_in[1];
    const float* w_qkv = (const float*)d_in[2];
    const float* b_qkv = (const float*)d_in[3];
    const float* w_out = (const float*)d_in[4];
    const float* b_out = (const float*)d_in[5];
    const float* ln1_g = (const float*)d_in[6];
    const float* ln1_b = (const float*)d_in[7];
    const float* ln2_g = (const float*)d_in[8];
    const float* ln2_b = (const float*)d_in[9];
    const float* w_ff1 = (const float*)d_in[10];
    const float* b_ff1 = (const float*)d_in[11];
    const float* w_ff2 = (const float*)d_in[12];
    const float* b_ff2 = (const float*)d_in[13];
    float* out = (float*)d_out;

    __half *normed, *q, *k, *v, *attn, *normed2, *ffh;
    __half *wqkv_h, *wout_h, *wff1_h, *wff2_h;
    float *x2;
    cudaGetSymbolAddress((void**)&normed,  g_normed);
    cudaGetSymbolAddress((void**)&q,       g_q);
    cudaGetSymbolAddress((void**)&k,       g_k);
    cudaGetSymbolAddress((void**)&v,       g_v);
    cudaGetSymbolAddress((void**)&attn,    g_attn);
    cudaGetSymbolAddress((void**)&x2,      g_x2);
    cudaGetSymbolAddress((void**)&normed2, g_normed2);
    cudaGetSymbolAddress((void**)&ffh,     g_ffh);
    cudaGetSymbolAddress((void**)&wqkv_h,  g_wqkv_h);
    cudaGetSymbolAddress((void**)&wout_h,  g_wout_h);
    cudaGetSymbolAddress((void**)&wff1_h,  g_wff1_h);
    cudaGetSymbolAddress((void**)&wff2_h,  g_wff2_h);

    const int smemT128 = GNST * (64 * ASTR + HBK * 136) * 2;   // 41,472 B
    const int smemT64  = GNST * (64 * ASTR + HBK * 72)  * 2;   // 29,184 B
    cudaFuncSetAttribute((const void*)hgemm64<128,3>, cudaFuncAttributeMaxDynamicSharedMemorySize, smemT128);
    cudaFuncSetAttribute((const void*)hgemm64<128,2>, cudaFuncAttributeMaxDynamicSharedMemorySize, smemT128);
    cudaFuncSetAttribute((const void*)hgemm64<64,1>,  cudaFuncAttributeMaxDynamicSharedMemorySize, smemT64);

    const int asmem = 4 * KVSTAGE * 2;   // 36,864 B
    cudaFuncSetAttribute(attn_h_kernel, cudaFuncAttributeMaxDynamicSharedMemorySize, asmem);

    // 0+1. fused: LN1 + weight convert
    ln_cvt_kernel<<<SEQ + 1184, 256>>>(
        x, ln1_g, ln1_b, normed,
        w_qkv, wqkv_h, DM * 3 * DM / 4,
        w_out, wout_h, DM * DM / 4,
        w_ff1, wff1_h, DM * DFF / 4,
        w_ff2, wff2_h, DFF * DM / 4);

    // 2. QKV projection + fused split/cosine-normalize/relayout (768 CTAs)
    hgemm64<128,3><<<dim3(SEQ / 64, 3 * DM / 128), 128, smemT128>>>(
        normed, wqkv_h, b_qkv, nullptr, nullptr, q, k, v, SEQ, 3 * DM, DM);
    // 3. attention
    attn_h_kernel<<<dim3(SEQ / 64, NH), 128, asmem>>>(q, k, v, lcc, attn);
    // 4. out projection + residual (512 CTAs)
    hgemm64<64,1><<<dim3(SEQ / 64, DM / 64), 128, smemT64>>>(
        attn, wout_h, b_out, x, x2, nullptr, nullptr, nullptr, SEQ, DM, DM);
    // 5. LN2
    ln_kernel<<<SEQ, 256>>>(x2, ln2_g, ln2_b, normed2);
    // 6. FF1 + exact GELU (1024 CTAs)
    hgemm64<128,2><<<dim3(SEQ / 64, DFF / 128), 128, smemT128>>>(
        normed2, wff1_h, b_ff1, nullptr, ffh, nullptr, nullptr, nullptr, SEQ, DFF, DM);
    // 7. FF2 + residual -> out (512 CTAs)
    hgemm64<64,1><<<dim3(SEQ / 64, DM / 64), 128, smemT64>>>(
        ffh, wff2_h, b_ff2, x2, out, nullptr, nullptr, nullptr, SEQ, DM, DFF);
}